// round 12
// baseline (speedup 1.0000x reference)
#include <cuda_runtime.h>
#include <cuda_fp16.h>
#include <cstdint>

#define BB 4
#define TT 2048
#define HH 16
#define DKk 64
#define DM 1024

// Scratch (static device globals: allocation-free, graph-capture safe)
__device__ __half g_q[BB * HH * TT * DKk];   // [B,H,T,Dk], scaled by 0.125*log2(e)
__device__ __half g_k[BB * HH * TT * DKk];
__device__ __half g_v[BB * HH * TT * DKk];
__device__ __half g_ao[BB * TT * DM];        // [B,T,D]
// fp16 copies of GEMM inputs
__device__ __half g_xq[BB * TT * DM];
__device__ __half g_xk[BB * TT * DM];
__device__ __half g_xv[BB * TT * DM];
__device__ __half g_wq[DM * DM];
__device__ __half g_wk[DM * DM];
__device__ __half g_wv[DM * DM];
__device__ __half g_wo[DM * DM];

// ---------------------------------------------------------------------------
// Baseline-PTX helpers (harness ptxas targets plain sm_103: no tcgen05;
// mma.sync m16n8k16 f16 + cp.async + ldmatrix are fine)
// ---------------------------------------------------------------------------
__device__ __forceinline__ void cp_async16(uint32_t s, const void* g) {
    asm volatile("cp.async.cg.shared.global [%0], [%1], 16;\n" :: "r"(s), "l"(g));
}
__device__ __forceinline__ void cp_commit() {
    asm volatile("cp.async.commit_group;\n" ::: "memory");
}
__device__ __forceinline__ void cp_wait1() {
    asm volatile("cp.async.wait_group 1;\n" ::: "memory");
}

__device__ __forceinline__ void ldmat_x4(uint32_t* r, uint32_t addr) {
    asm volatile("ldmatrix.sync.aligned.m8n8.x4.shared.b16 {%0,%1,%2,%3}, [%4];"
                 : "=r"(r[0]), "=r"(r[1]), "=r"(r[2]), "=r"(r[3]) : "r"(addr));
}
__device__ __forceinline__ void ldmat_x4_t(uint32_t* r, uint32_t addr) {
    asm volatile("ldmatrix.sync.aligned.m8n8.x4.trans.shared.b16 {%0,%1,%2,%3}, [%4];"
                 : "=r"(r[0]), "=r"(r[1]), "=r"(r[2]), "=r"(r[3]) : "r"(addr));
}

// D += A(16x16 f16, row) * B(16x8 f16, col), fp32 accumulate
__device__ __forceinline__ void mma_f16(float* c, const uint32_t* a, const uint32_t* b) {
    asm volatile(
        "mma.sync.aligned.m16n8k16.row.col.f32.f16.f16.f32 "
        "{%0,%1,%2,%3}, {%4,%5,%6,%7}, {%8,%9}, {%0,%1,%2,%3};"
        : "+f"(c[0]), "+f"(c[1]), "+f"(c[2]), "+f"(c[3])
        : "r"(a[0]), "r"(a[1]), "r"(a[2]), "r"(a[3]), "r"(b[0]), "r"(b[1]));
}

// ---------------------------------------------------------------------------
// fp32 -> fp16 conversion pre-pass: two arrays per launch (blockIdx.y selects)
// ---------------------------------------------------------------------------
__global__ __launch_bounds__(256)
void cvt2_kernel(const float4* __restrict__ in0, __half2* __restrict__ out0, int n0,
                 const float4* __restrict__ in1, __half2* __restrict__ out1, int n1)
{
    const float4* in = blockIdx.y ? in1 : in0;
    __half2* out = blockIdx.y ? out1 : out0;
    const int n4 = blockIdx.y ? n1 : n0;
    int i = blockIdx.x * blockDim.x + threadIdx.x;
    const int stride = gridDim.x * blockDim.x;
    for (; i < n4; i += stride) {
        float4 v = in[i];
        out[2 * i + 0] = __floats2half2_rn(v.x, v.y);
        out[2 * i + 1] = __floats2half2_rn(v.z, v.w);
    }
}

// ---------------------------------------------------------------------------
// Tensor-core fp16 GEMM: C = (X @ W^T + bias) * scale
// CTA 128x256, BK=64, 3-stage cp.async, 8 warps (2x4), warp tile 64x64:
// per k16-step 8 ldmatrix feed 32 mma (4:1, was 2.7:1).
// 1 CTA/SM (reg-bound: 128 accum regs). XOR-swizzled 64-half rows.
// K accumulation order identical to round-10/11 kernels (bit-identical C).
// ---------------------------------------------------------------------------
#define A_HALVES_G (128 * 64)
#define B_HALVES_G (256 * 64)
#define STG_HALVES (A_HALVES_G + B_HALVES_G)        // 24576 halves
#define GEMM_SMEM_BYTES (3 * STG_HALVES * 2)        // 147456

template <int HEAD_LAYOUT>
__global__ __launch_bounds__(256, 1)
void gemm_f16_kernel(const __half* __restrict__ X, const __half* __restrict__ W,
                     const float* __restrict__ bias, void* __restrict__ outv,
                     int M, int N, int K, float scale)
{
    extern __shared__ __half smh[];
    const uint32_t smb = (uint32_t)__cvta_generic_to_shared(smh);
    const int tid = threadIdx.x;
    const int wid = tid >> 5;
    const int lane = tid & 31;
    const int g = lane >> 2;
    const int tig = lane & 3;
    const int q8 = lane >> 3;
    const int rr = lane & 7;
    const int qc = q8 >> 1;
    const int rb = (q8 & 1) * 8;
    const int wm = wid >> 2;         // 0..1 -> 64 rows
    const int wn = wid & 3;          // 0..3 -> 64 cols
    const int m0 = blockIdx.y * 128;
    const int n0 = blockIdx.x * 256;
    const int KT = K >> 6;

    uint32_t arow[4], brow[4];
#pragma unroll
    for (int fm = 0; fm < 4; fm++)
        arow[fm] = (uint32_t)((wm * 64 + fm * 16 + rb + rr) * 64);
#pragma unroll
    for (int p = 0; p < 4; p++)
        brow[p] = (uint32_t)(A_HALVES_G + (wn * 64 + p * 16 + rb + rr) * 64);

    // Per stage: A 128x8 chunks (1024), B 256x8 chunks (2048) -> 12/thread
    auto load_tile = [&](int tile) {
        const int k0 = tile << 6;
        const uint32_t base = smb + (uint32_t)(tile % 3) * (STG_HALVES * 2);
#pragma unroll
        for (int i = 0; i < 4; i++) {
            int idx = tid + (i << 8);              // 0..1023
            int r = idx >> 3;
            int c = idx & 7;
            uint32_t off = (uint32_t)((r * 64 + ((c ^ (r & 7)) * 8)) * 2);
            cp_async16(base + off, X + (size_t)(m0 + r) * K + k0 + c * 8);
        }
#pragma unroll
        for (int i = 0; i < 8; i++) {
            int idx = tid + (i << 8);              // 0..2047
            int r = idx >> 3;                      // 0..255
            int c = idx & 7;
            uint32_t off = (uint32_t)((r * 64 + ((c ^ (r & 7)) * 8)) * 2);
            cp_async16(base + A_HALVES_G * 2 + off, W + (size_t)(n0 + r) * K + k0 + c * 8);
        }
    };

    load_tile(0); cp_commit();
    load_tile(1); cp_commit();

    float acc[4][8][4];
#pragma unroll
    for (int fm = 0; fm < 4; fm++)
#pragma unroll
        for (int fn = 0; fn < 8; fn++)
#pragma unroll
            for (int e = 0; e < 4; e++) acc[fm][fn][e] = 0.0f;

    for (int kt = 0; kt < KT; kt++) {
        cp_wait1();
        __syncthreads();
        if (kt + 2 < KT) load_tile(kt + 2);
        cp_commit();

        const uint32_t stage = smb + (uint32_t)(kt % 3) * (STG_HALVES * 2);

#pragma unroll
        for (int ks = 0; ks < 4; ks++) {
            const uint32_t ch = (uint32_t)((((2 * ks + qc) ^ rr) * 8) * 2);  // bytes
            uint32_t a[4][4], bb[4][4];
#pragma unroll
            for (int fm = 0; fm < 4; fm++) ldmat_x4(a[fm], stage + arow[fm] * 2 + ch);
#pragma unroll
            for (int p = 0; p < 4; p++) ldmat_x4(bb[p], stage + brow[p] * 2 + ch);
#pragma unroll
            for (int fm = 0; fm < 4; fm++)
#pragma unroll
                for (int fn = 0; fn < 8; fn++) {
                    uint32_t b2[2] = {bb[fn >> 1][fn & 1], bb[fn >> 1][2 + (fn & 1)]};
                    mma_f16(acc[fm][fn], a[fm], b2);
                }
        }
    }

#pragma unroll
    for (int fm = 0; fm < 4; fm++) {
#pragma unroll
        for (int fn = 0; fn < 8; fn++) {
            int n = n0 + wn * 64 + fn * 8 + 2 * tig;
            float bx = __ldg(&bias[n]);
            float by = __ldg(&bias[n + 1]);
#pragma unroll
            for (int half = 0; half < 2; half++) {
                int m = m0 + wm * 64 + fm * 16 + g + half * 8;
                float ox = (acc[fm][fn][half * 2 + 0] + bx) * scale;
                float oy = (acc[fm][fn][half * 2 + 1] + by) * scale;
                if (HEAD_LAYOUT) {
                    __half* out = (__half*)outv;
                    int b = m / TT, t = m % TT;
                    int h = n / DKk, dk = n % DKk;
                    *(__half2*)&out[(((size_t)b * HH + h) * TT + t) * DKk + dk] =
                        __floats2half2_rn(ox, oy);
                } else {
                    float* out = (float*)outv;
                    *(float2*)&out[(size_t)m * N + n] = make_float2(ox, oy);
                }
            }
        }
    }
}

// ---------------------------------------------------------------------------
// Tensor-core fp16 flash attention (unchanged from round 11).
// BQ=128, BK=64, triple-buffered KV, 8 warps, register-resident P,
// l via mma vs ones, heavy q-tiles first. smem = 65536 B.
// ---------------------------------------------------------------------------
#define Q_OFF 0
#define K_OFF (128 * 64)
#define KVBUF (64 * 64)
#define V_OFF (K_OFF + 3 * KVBUF)
#define FA_HALVES (V_OFF + 3 * KVBUF)
#define FA_SMEM_BYTES (FA_HALVES * 2)          // 65536

__global__ __launch_bounds__(256, 2)
void flash_f16_kernel(const __half* __restrict__ Q, const __half* __restrict__ K,
                      const __half* __restrict__ V, __half* __restrict__ out)
{
    extern __shared__ __half smh[];
    const uint32_t smb = (uint32_t)__cvta_generic_to_shared(smh);
    const int tid = threadIdx.x;
    const int wid = tid >> 5;
    const int lane = tid & 31;
    const int g = lane >> 2;
    const int tig = lane & 3;
    const int q8 = lane >> 3;
    const int rr = lane & 7;
    const int qc = q8 >> 1;
    const int rb = (q8 & 1) * 8;
    const int qt = gridDim.x - 1 - blockIdx.x;   // heavy tiles first
    const int bh = blockIdx.y;

    const __half* Qb = Q + ((size_t)bh * TT + qt * 128) * DKk;
    const __half* Kb = K + (size_t)bh * TT * DKk;
    const __half* Vb = V + (size_t)bh * TT * DKk;

#pragma unroll
    for (int i = 0; i < 4; i++) {
        int idx = tid + (i << 8);
        int r = idx >> 3;
        int c = idx & 7;
        uint32_t dst = smb + (uint32_t)((r * 64 + ((c ^ (r & 7)) * 8)) * 2);
        cp_async16(dst, Qb + r * 64 + c * 8);
    }

    auto load_kv = [&](int kt) {
        const int buf = kt % 3;
        const __half* kp = Kb + (size_t)kt * 64 * DKk;
        const __half* vp = Vb + (size_t)kt * 64 * DKk;
#pragma unroll
        for (int i = 0; i < 2; i++) {
            int idx = tid + (i << 8);
            int r = idx >> 3;
            int c = idx & 7;
            uint32_t off = (uint32_t)((r * 64 + ((c ^ (r & 7)) * 8)) * 2);
            uint32_t src_off = (uint32_t)(r * 64 + c * 8);
            cp_async16(smb + (K_OFF + buf * KVBUF) * 2 + off, kp + src_off);
            cp_async16(smb + (V_OFF + buf * KVBUF) * 2 + off, vp + src_off);
        }
    };

    load_kv(0);
    cp_commit();
    load_kv(1);
    cp_commit();

    cp_wait1();
    __syncthreads();
    const uint32_t qrow_h = (uint32_t)((wid * 16 + rb + rr) * 64);
    uint32_t qf[4][4];
#pragma unroll
    for (int ks = 0; ks < 4; ks++) {
        const uint32_t ch = (uint32_t)(((2 * ks + qc) ^ rr) * 8);
        ldmat_x4(qf[ks], smb + (qrow_h + ch) * 2);
    }

    float m0r = -1e30f, m1r = -1e30f;
    float o[8][4], ol[4];
#pragma unroll
    for (int nf = 0; nf < 8; nf++)
#pragma unroll
        for (int e = 0; e < 4; e++) o[nf][e] = 0.0f;
#pragma unroll
    for (int e = 0; e < 4; e++) ol[e] = 0.0f;

    const uint32_t ones2[2] = {0x3C003C00u, 0x3C003C00u};
    const int nkt = 2 * qt + 2;
    const int row0 = wid * 16 + g;

    for (int kt = 0; kt < nkt; kt++) {
        if (kt) { cp_wait1(); __syncthreads(); }
        if (kt + 2 < nkt) load_kv(kt + 2);
        cp_commit();

        const int buf = kt % 3;
        const uint32_t kbuf_h = (uint32_t)(K_OFF + buf * KVBUF);
        const uint32_t vbuf_h = (uint32_t)(V_OFF + buf * KVBUF);

        float s[8][4];
#pragma unroll
        for (int nf = 0; nf < 8; nf++)
#pragma unroll
            for (int e = 0; e < 4; e++) s[nf][e] = 0.0f;

#pragma unroll
        for (int ks = 0; ks < 4; ks++) {
            uint32_t bb[4][4];
            const uint32_t ch = (uint32_t)(((2 * ks + qc) ^ rr) * 8);
#pragma unroll
            for (int p = 0; p < 4; p++) {
                uint32_t krow_h = kbuf_h + (uint32_t)((p * 16 + rb + rr) * 64);
                ldmat_x4(bb[p], smb + (krow_h + ch) * 2);
            }
#pragma unroll
            for (int nf = 0; nf < 8; nf++) {
                uint32_t b2[2] = {bb[nf >> 1][nf & 1], bb[nf >> 1][2 + (nf & 1)]};
                mma_f16(s[nf], qf[ks], b2);
            }
        }

        if (kt >= 2 * qt) {
            const int qg0 = qt * 128 + row0;
            const int qg1 = qg0 + 8;
#pragma unroll
            for (int nf = 0; nf < 8; nf++) {
                int kg = kt * 64 + nf * 8 + 2 * tig;
                if (kg > qg0) s[nf][0] = -1e30f;
                if (kg + 1 > qg0) s[nf][1] = -1e30f;
                if (kg > qg1) s[nf][2] = -1e30f;
                if (kg + 1 > qg1) s[nf][3] = -1e30f;
            }
        }

        float mx0 = -1e30f, mx1 = -1e30f;
#pragma unroll
        for (int nf = 0; nf < 8; nf++) {
            mx0 = fmaxf(mx0, fmaxf(s[nf][0], s[nf][1]));
            mx1 = fmaxf(mx1, fmaxf(s[nf][2], s[nf][3]));
        }
        mx0 = fmaxf(mx0, __shfl_xor_sync(0xffffffffu, mx0, 1));
        mx0 = fmaxf(mx0, __shfl_xor_sync(0xffffffffu, mx0, 2));
        mx1 = fmaxf(mx1, __shfl_xor_sync(0xffffffffu, mx1, 1));
        mx1 = fmaxf(mx1, __shfl_xor_sync(0xffffffffu, mx1, 2));

        float mn0 = fmaxf(m0r, mx0);
        float mn1 = fmaxf(m1r, mx1);
        float al0 = exp2f(m0r - mn0);
        float al1 = exp2f(m1r - mn1);
        m0r = mn0; m1r = mn1;

        uint32_t pa[4][4];
#pragma unroll
        for (int nf = 0; nf < 8; nf++) {
            __half2 p01 = h2exp2(__floats2half2_rn(s[nf][0] - mn0, s[nf][1] - mn0));
            __half2 p23 = h2exp2(__floats2half2_rn(s[nf][2] - mn1, s[nf][3] - mn1));
            const int ks = nf >> 1;
            const int hi = (nf & 1) * 2;
            pa[ks][hi + 0] = *(const uint32_t*)&p01;
            pa[ks][hi + 1] = *(const uint32_t*)&p23;
        }

#pragma unroll
        for (int nf = 0; nf < 8; nf++) {
            o[nf][0] *= al0; o[nf][1] *= al0;
            o[nf][2] *= al1; o[nf][3] *= al1;
        }
        ol[0] *= al0; ol[1] *= al0; ol[2] *= al1; ol[3] *= al1;

#pragma unroll
        for (int ks = 0; ks < 4; ks++) {
            mma_f16(ol, pa[ks], ones2);
            const uint32_t vrow_h = vbuf_h + (uint32_t)((16 * ks + rb + rr) * 64);
#pragma unroll
            for (int p = 0; p < 4; p++) {
                uint32_t vv[4];
                const uint32_t ch = (uint32_t)(((2 * p + qc) ^ rr) * 8);
                ldmat_x4_t(vv, smb + (vrow_h + ch) * 2);
                mma_f16(o[2 * p + 0], pa[ks], &vv[0]);
                mma_f16(o[2 * p + 1], pa[ks], &vv[2]);
            }
        }
    }

    const int b = bh >> 4;
    const int h = bh & 15;
    const float li0 = 1.0f / ol[0];
    const float li1 = 1.0f / ol[2];
    const int qg0 = qt * 128 + row0;
#pragma unroll
    for (int nf = 0; nf < 8; nf++) {
        int col = h * DKk + nf * 8 + 2 * tig;
        *(__half2*)&out[((size_t)b * TT + qg0) * DM + col] =
            __floats2half2_rn(o[nf][0] * li0, o[nf][1] * li0);
        *(__half2*)&out[((size_t)b * TT + qg0 + 8) * DM + col] =
            __floats2half2_rn(o[nf][2] * li1, o[nf][3] * li1);
    }
}

// ---------------------------------------------------------------------------
extern "C" void kernel_launch(void* const* d_in, const int* in_sizes, int n_in,
                              void* d_out, int out_size)
{
    const float* query = (const float*)d_in[0];
    const float* key   = (const float*)d_in[1];
    const float* value = (const float*)d_in[2];
    // d_in[3] = mask (causal tril, known statically — unused)
    const float* Wq = (const float*)d_in[4];
    const float* bq = (const float*)d_in[5];
    const float* Wk = (const float*)d_in[6];
    const float* bk = (const float*)d_in[7];
    const float* Wv = (const float*)d_in[8];
    const float* bv = (const float*)d_in[9];
    const float* Wo = (const float*)d_in[10];
    const float* bo = (const float*)d_in[11];
    float* out = (float*)d_out;

    __half *q, *k, *v, *ao, *xq, *xk, *xv, *wq, *wk, *wv, *wo;
    cudaGetSymbolAddress((void**)&q,  g_q);
    cudaGetSymbolAddress((void**)&k,  g_k);
    cudaGetSymbolAddress((void**)&v,  g_v);
    cudaGetSymbolAddress((void**)&ao, g_ao);
    cudaGetSymbolAddress((void**)&xq, g_xq);
    cudaGetSymbolAddress((void**)&xk, g_xk);
    cudaGetSymbolAddress((void**)&xv, g_xv);
    cudaGetSymbolAddress((void**)&wq, g_wq);
    cudaGetSymbolAddress((void**)&wk, g_wk);
    cudaGetSymbolAddress((void**)&wv, g_wv);
    cudaGetSymbolAddress((void**)&wo, g_wo);

    cudaFuncSetAttribute(gemm_f16_kernel<1>,
                         cudaFuncAttributeMaxDynamicSharedMemorySize, GEMM_SMEM_BYTES);
    cudaFuncSetAttribute(gemm_f16_kernel<0>,
                         cudaFuncAttributeMaxDynamicSharedMemorySize, GEMM_SMEM_BYTES);
    cudaFuncSetAttribute(flash_f16_kernel,
                         cudaFuncAttributeMaxDynamicSharedMemorySize, FA_SMEM_BYTES);

    static cudaStream_t s1 = nullptr, s2 = nullptr, s3 = nullptr;
    static cudaEvent_t ef = nullptr, ej1 = nullptr, ej2 = nullptr, ej3 = nullptr;
    if (!s1) {
        cudaStreamCreateWithFlags(&s1, cudaStreamNonBlocking);
        cudaStreamCreateWithFlags(&s2, cudaStreamNonBlocking);
        cudaStreamCreateWithFlags(&s3, cudaStreamNonBlocking);
        cudaEventCreateWithFlags(&ef,  cudaEventDisableTiming);
        cudaEventCreateWithFlags(&ej1, cudaEventDisableTiming);
        cudaEventCreateWithFlags(&ej2, cudaEventDisableTiming);
        cudaEventCreateWithFlags(&ej3, cudaEventDisableTiming);
    }

    const int M = BB * TT;               // 8192
    const int NX4 = M * DM / 4;
    const int NW4 = DM * DM / 4;
    dim3 gemm_grid(DM / 256, M / 128);   // (4, 64) = 256 CTAs
    dim3 rgrid(512, 2);
    const float qscale = 0.125f * 1.4426950408889634f;

    // Fork
    cudaEventRecord(ef, 0);
    cudaStreamWaitEvent(s1, ef, 0);
    cudaStreamWaitEvent(s2, ef, 0);
    cudaStreamWaitEvent(s3, ef, 0);

    // Q chain (stream 0)
    cvt2_kernel<<<rgrid, 256, 0, 0>>>((const float4*)query, (__half2*)xq, NX4,
                                      (const float4*)Wq, (__half2*)wq, NW4);
    gemm_f16_kernel<1><<<gemm_grid, 256, GEMM_SMEM_BYTES, 0>>>(xq, wq, bq, q, M, DM, DM, qscale);

    // K chain (s1)
    cvt2_kernel<<<rgrid, 256, 0, s1>>>((const float4*)key, (__half2*)xk, NX4,
                                       (const float4*)Wk, (__half2*)wk, NW4);
    gemm_f16_kernel<1><<<gemm_grid, 256, GEMM_SMEM_BYTES, s1>>>(xk, wk, bk, k, M, DM, DM, 1.0f);
    cudaEventRecord(ej1, s1);

    // V chain (s2)
    cvt2_kernel<<<rgrid, 256, 0, s2>>>((const float4*)value, (__half2*)xv, NX4,
                                       (const float4*)Wv, (__half2*)wv, NW4);
    gemm_f16_kernel<1><<<gemm_grid, 256, GEMM_SMEM_BYTES, s2>>>(xv, wv, bv, v, M, DM, DM, 1.0f);
    cudaEventRecord(ej2, s2);

    // Wo conversion (s3)
    cvt2_kernel<<<dim3(512, 1), 256, 0, s3>>>((const float4*)Wo, (__half2*)wo, NW4,
                                              (const float4*)Wo, (__half2*)wo, 0);
    cudaEventRecord(ej3, s3);

    // Join K and V before flash
    cudaStreamWaitEvent(0, ej1, 0);
    cudaStreamWaitEvent(0, ej2, 0);

    dim3 fa_grid(TT / 128, BB * HH);     // (16, 64)
    flash_f16_kernel<<<fa_grid, 256, FA_SMEM_BYTES, 0>>>(q, k, v, ao);

    // Output projection
    cudaStreamWaitEvent(0, ej3, 0);
    gemm_f16_kernel<0><<<gemm_grid, 256, GEMM_SMEM_BYTES, 0>>>(ao, wo, bo, out, M, DM, DM, 1.0f);
}

// round 13
// speedup vs baseline: 1.0827x; 1.0827x over previous
#include <cuda_runtime.h>
#include <cuda_fp16.h>
#include <cstdint>

#define BB 4
#define TT 2048
#define HH 16
#define DKk 64
#define DM 1024

// Scratch (static device globals: allocation-free, graph-capture safe)
__device__ __half g_q[BB * HH * TT * DKk];   // [B,H,T,Dk], scaled by 0.125*log2(e)
__device__ __half g_k[BB * HH * TT * DKk];
__device__ __half g_v[BB * HH * TT * DKk];
__device__ __half g_ao[BB * TT * DM];        // [B,T,D]
// fp16 copies of GEMM inputs
__device__ __half g_xq[BB * TT * DM];
__device__ __half g_xk[BB * TT * DM];
__device__ __half g_xv[BB * TT * DM];
__device__ __half g_wq[DM * DM];
__device__ __half g_wk[DM * DM];
__device__ __half g_wv[DM * DM];
__device__ __half g_wo[DM * DM];

// ---------------------------------------------------------------------------
// Baseline-PTX helpers (harness ptxas targets plain sm_103: no tcgen05;
// mma.sync m16n8k16 f16 + cp.async + ldmatrix are fine)
// ---------------------------------------------------------------------------
__device__ __forceinline__ void cp_async16(uint32_t s, const void* g) {
    asm volatile("cp.async.cg.shared.global [%0], [%1], 16;\n" :: "r"(s), "l"(g));
}
__device__ __forceinline__ void cp_commit() {
    asm volatile("cp.async.commit_group;\n" ::: "memory");
}
__device__ __forceinline__ void cp_wait1() {
    asm volatile("cp.async.wait_group 1;\n" ::: "memory");
}

__device__ __forceinline__ void ldmat_x4(uint32_t* r, uint32_t addr) {
    asm volatile("ldmatrix.sync.aligned.m8n8.x4.shared.b16 {%0,%1,%2,%3}, [%4];"
                 : "=r"(r[0]), "=r"(r[1]), "=r"(r[2]), "=r"(r[3]) : "r"(addr));
}
__device__ __forceinline__ void ldmat_x4_t(uint32_t* r, uint32_t addr) {
    asm volatile("ldmatrix.sync.aligned.m8n8.x4.trans.shared.b16 {%0,%1,%2,%3}, [%4];"
                 : "=r"(r[0]), "=r"(r[1]), "=r"(r[2]), "=r"(r[3]) : "r"(addr));
}

// D += A(16x16 f16, row) * B(16x8 f16, col), fp32 accumulate
__device__ __forceinline__ void mma_f16(float* c, const uint32_t* a, const uint32_t* b) {
    asm volatile(
        "mma.sync.aligned.m16n8k16.row.col.f32.f16.f16.f32 "
        "{%0,%1,%2,%3}, {%4,%5,%6,%7}, {%8,%9}, {%0,%1,%2,%3};"
        : "+f"(c[0]), "+f"(c[1]), "+f"(c[2]), "+f"(c[3])
        : "r"(a[0]), "r"(a[1]), "r"(a[2]), "r"(a[3]), "r"(b[0]), "r"(b[1]));
}

// ---------------------------------------------------------------------------
// fp32 -> fp16 conversion pre-pass: two arrays per launch (blockIdx.y selects)
// ---------------------------------------------------------------------------
__global__ __launch_bounds__(256)
void cvt2_kernel(const float4* __restrict__ in0, __half2* __restrict__ out0, int n0,
                 const float4* __restrict__ in1, __half2* __restrict__ out1, int n1)
{
    const float4* in = blockIdx.y ? in1 : in0;
    __half2* out = blockIdx.y ? out1 : out0;
    const int n4 = blockIdx.y ? n1 : n0;
    int i = blockIdx.x * blockDim.x + threadIdx.x;
    const int stride = gridDim.x * blockDim.x;
    for (; i < n4; i += stride) {
        float4 v = in[i];
        out[2 * i + 0] = __floats2half2_rn(v.x, v.y);
        out[2 * i + 1] = __floats2half2_rn(v.z, v.w);
    }
}

// ---------------------------------------------------------------------------
// Tensor-core fp16 GEMM body (round-11 proven config):
// CTA 128x128, BK=64, 3-stage cp.async, 8 warps (2x4), warp tile 64x32,
// XOR-swizzled 64-half rows, 2 CTAs/SM.
// ---------------------------------------------------------------------------
#define STG_HALVES (2 * 128 * 64)
#define GEMM_SMEM_BYTES (3 * STG_HALVES * 2)   // 98304

template <int HEAD_LAYOUT>
__device__ __forceinline__
void gemm_body(const __half* __restrict__ X, const __half* __restrict__ W,
               const float* __restrict__ bias, void* __restrict__ outv,
               int N, int K, float scale, int m0, int n0)
{
    extern __shared__ __half smh[];
    const uint32_t smb = (uint32_t)__cvta_generic_to_shared(smh);
    const int tid = threadIdx.x;
    const int wid = tid >> 5;
    const int lane = tid & 31;
    const int g = lane >> 2;
    const int tig = lane & 3;
    const int q8 = lane >> 3;
    const int rr = lane & 7;
    const int qc = q8 >> 1;
    const int rb = (q8 & 1) * 8;
    const int wm = wid >> 2;
    const int wn = wid & 3;
    const int KT = K >> 6;

    uint32_t arow[4], brow[2];
#pragma unroll
    for (int fm = 0; fm < 4; fm++)
        arow[fm] = (uint32_t)((wm * 64 + fm * 16 + rb + rr) * 64);
#pragma unroll
    for (int p = 0; p < 2; p++)
        brow[p] = (uint32_t)(128 * 64 + (wn * 32 + p * 16 + rb + rr) * 64);

    auto load_tile = [&](int tile) {
        const int k0 = tile << 6;
        const uint32_t base = smb + (uint32_t)(tile % 3) * (STG_HALVES * 2);
#pragma unroll
        for (int i = 0; i < 4; i++) {
            int idx = tid + (i << 8);
            int r = idx >> 3;
            int c = idx & 7;
            uint32_t off = (uint32_t)((r * 64 + ((c ^ (r & 7)) * 8)) * 2);
            cp_async16(base + off, X + (size_t)(m0 + r) * K + k0 + c * 8);
            cp_async16(base + 128 * 64 * 2 + off, W + (size_t)(n0 + r) * K + k0 + c * 8);
        }
    };

    load_tile(0); cp_commit();
    load_tile(1); cp_commit();

    float acc[4][4][4];
#pragma unroll
    for (int fm = 0; fm < 4; fm++)
#pragma unroll
        for (int fn = 0; fn < 4; fn++)
#pragma unroll
            for (int e = 0; e < 4; e++) acc[fm][fn][e] = 0.0f;

    for (int kt = 0; kt < KT; kt++) {
        cp_wait1();
        __syncthreads();
        if (kt + 2 < KT) load_tile(kt + 2);
        cp_commit();

        const uint32_t stage = smb + (uint32_t)(kt % 3) * (STG_HALVES * 2);

#pragma unroll
        for (int ks = 0; ks < 4; ks++) {
            const uint32_t ch = (uint32_t)((((2 * ks + qc) ^ rr) * 8) * 2);
            uint32_t a[4][4], bb[2][4];
#pragma unroll
            for (int fm = 0; fm < 4; fm++) ldmat_x4(a[fm], stage + arow[fm] * 2 + ch);
#pragma unroll
            for (int p = 0; p < 2; p++) ldmat_x4(bb[p], stage + brow[p] * 2 + ch);
#pragma unroll
            for (int fm = 0; fm < 4; fm++)
#pragma unroll
                for (int fn = 0; fn < 4; fn++) {
                    uint32_t b2[2] = {bb[fn >> 1][fn & 1], bb[fn >> 1][2 + (fn & 1)]};
                    mma_f16(acc[fm][fn], a[fm], b2);
                }
        }
    }

#pragma unroll
    for (int fm = 0; fm < 4; fm++) {
#pragma unroll
        for (int fn = 0; fn < 4; fn++) {
            int n = n0 + wn * 32 + fn * 8 + 2 * tig;
            float bx = __ldg(&bias[n]);
            float by = __ldg(&bias[n + 1]);
#pragma unroll
            for (int half = 0; half < 2; half++) {
                int m = m0 + wm * 64 + fm * 16 + g + half * 8;
                float ox = (acc[fm][fn][half * 2 + 0] + bx) * scale;
                float oy = (acc[fm][fn][half * 2 + 1] + by) * scale;
                if (HEAD_LAYOUT) {
                    __half* out = (__half*)outv;
                    int b = m / TT, t = m % TT;
                    int h = n / DKk, dk = n % DKk;
                    *(__half2*)&out[(((size_t)b * HH + h) * TT + t) * DKk + dk] =
                        __floats2half2_rn(ox, oy);
                } else {
                    float* out = (float*)outv;
                    *(float2*)&out[(size_t)m * N + n] = make_float2(ox, oy);
                }
            }
        }
    }
}

// Head-layout projection GEMM (full M range)
__global__ __launch_bounds__(256, 2)
void gemm_head_kernel(const __half* __restrict__ X, const __half* __restrict__ W,
                      const float* __restrict__ bias, __half* __restrict__ out,
                      float scale)
{
    gemm_body<1>(X, W, bias, out, DM, DM, scale, blockIdx.y * 128, blockIdx.x * 128);
}

// Output GEMM over HALF the rows: row_half=0 -> t in [0,1024), 1 -> [1024,2048).
// blockIdx.y in [0,32): b = y>>3, tblk = y&7.
__global__ __launch_bounds__(256, 2)
void gemm_out_half_kernel(const __half* __restrict__ X, const __half* __restrict__ W,
                          const float* __restrict__ bias, float* __restrict__ out,
                          int row_half)
{
    const int y = blockIdx.y;
    const int m0 = (y >> 3) * TT + row_half * 1024 + (y & 7) * 128;
    gemm_body<0>(X, W, bias, out, DM, DM, 1.0f, m0, blockIdx.x * 128);
}

// ---------------------------------------------------------------------------
// Tensor-core fp16 flash attention (round-11 config + qt_base for split
// launches). BQ=128, BK=64, triple-buffered KV, 8 warps, register-resident P,
// l via mma vs ones, heavy q-tiles first within each launch. smem = 65536 B.
// ---------------------------------------------------------------------------
#define Q_OFF 0
#define K_OFF (128 * 64)
#define KVBUF (64 * 64)
#define V_OFF (K_OFF + 3 * KVBUF)
#define FA_HALVES (V_OFF + 3 * KVBUF)
#define FA_SMEM_BYTES (FA_HALVES * 2)          // 65536

__global__ __launch_bounds__(256, 2)
void flash_f16_kernel(const __half* __restrict__ Q, const __half* __restrict__ K,
                      const __half* __restrict__ V, __half* __restrict__ out,
                      int qt_base)
{
    extern __shared__ __half smh[];
    const uint32_t smb = (uint32_t)__cvta_generic_to_shared(smh);
    const int tid = threadIdx.x;
    const int wid = tid >> 5;
    const int lane = tid & 31;
    const int g = lane >> 2;
    const int tig = lane & 3;
    const int q8 = lane >> 3;
    const int rr = lane & 7;
    const int qc = q8 >> 1;
    const int rb = (q8 & 1) * 8;
    const int qt = qt_base + gridDim.x - 1 - blockIdx.x;   // heavy tiles first
    const int bh = blockIdx.y;

    const __half* Qb = Q + ((size_t)bh * TT + qt * 128) * DKk;
    const __half* Kb = K + (size_t)bh * TT * DKk;
    const __half* Vb = V + (size_t)bh * TT * DKk;

#pragma unroll
    for (int i = 0; i < 4; i++) {
        int idx = tid + (i << 8);
        int r = idx >> 3;
        int c = idx & 7;
        uint32_t dst = smb + (uint32_t)((r * 64 + ((c ^ (r & 7)) * 8)) * 2);
        cp_async16(dst, Qb + r * 64 + c * 8);
    }

    auto load_kv = [&](int kt) {
        const int buf = kt % 3;
        const __half* kp = Kb + (size_t)kt * 64 * DKk;
        const __half* vp = Vb + (size_t)kt * 64 * DKk;
#pragma unroll
        for (int i = 0; i < 2; i++) {
            int idx = tid + (i << 8);
            int r = idx >> 3;
            int c = idx & 7;
            uint32_t off = (uint32_t)((r * 64 + ((c ^ (r & 7)) * 8)) * 2);
            uint32_t src_off = (uint32_t)(r * 64 + c * 8);
            cp_async16(smb + (K_OFF + buf * KVBUF) * 2 + off, kp + src_off);
            cp_async16(smb + (V_OFF + buf * KVBUF) * 2 + off, vp + src_off);
        }
    };

    load_kv(0);
    cp_commit();
    load_kv(1);
    cp_commit();

    cp_wait1();
    __syncthreads();
    const uint32_t qrow_h = (uint32_t)((wid * 16 + rb + rr) * 64);
    uint32_t qf[4][4];
#pragma unroll
    for (int ks = 0; ks < 4; ks++) {
        const uint32_t ch = (uint32_t)(((2 * ks + qc) ^ rr) * 8);
        ldmat_x4(qf[ks], smb + (qrow_h + ch) * 2);
    }

    float m0r = -1e30f, m1r = -1e30f;
    float o[8][4], ol[4];
#pragma unroll
    for (int nf = 0; nf < 8; nf++)
#pragma unroll
        for (int e = 0; e < 4; e++) o[nf][e] = 0.0f;
#pragma unroll
    for (int e = 0; e < 4; e++) ol[e] = 0.0f;

    const uint32_t ones2[2] = {0x3C003C00u, 0x3C003C00u};
    const int nkt = 2 * qt + 2;
    const int row0 = wid * 16 + g;

    for (int kt = 0; kt < nkt; kt++) {
        if (kt) { cp_wait1(); __syncthreads(); }
        if (kt + 2 < nkt) load_kv(kt + 2);
        cp_commit();

        const int buf = kt % 3;
        const uint32_t kbuf_h = (uint32_t)(K_OFF + buf * KVBUF);
        const uint32_t vbuf_h = (uint32_t)(V_OFF + buf * KVBUF);

        float s[8][4];
#pragma unroll
        for (int nf = 0; nf < 8; nf++)
#pragma unroll
            for (int e = 0; e < 4; e++) s[nf][e] = 0.0f;

#pragma unroll
        for (int ks = 0; ks < 4; ks++) {
            uint32_t bb[4][4];
            const uint32_t ch = (uint32_t)(((2 * ks + qc) ^ rr) * 8);
#pragma unroll
            for (int p = 0; p < 4; p++) {
                uint32_t krow_h = kbuf_h + (uint32_t)((p * 16 + rb + rr) * 64);
                ldmat_x4(bb[p], smb + (krow_h + ch) * 2);
            }
#pragma unroll
            for (int nf = 0; nf < 8; nf++) {
                uint32_t b2[2] = {bb[nf >> 1][nf & 1], bb[nf >> 1][2 + (nf & 1)]};
                mma_f16(s[nf], qf[ks], b2);
            }
        }

        if (kt >= 2 * qt) {
            const int qg0 = qt * 128 + row0;
            const int qg1 = qg0 + 8;
#pragma unroll
            for (int nf = 0; nf < 8; nf++) {
                int kg = kt * 64 + nf * 8 + 2 * tig;
                if (kg > qg0) s[nf][0] = -1e30f;
                if (kg + 1 > qg0) s[nf][1] = -1e30f;
                if (kg > qg1) s[nf][2] = -1e30f;
                if (kg + 1 > qg1) s[nf][3] = -1e30f;
            }
        }

        float mx0 = -1e30f, mx1 = -1e30f;
#pragma unroll
        for (int nf = 0; nf < 8; nf++) {
            mx0 = fmaxf(mx0, fmaxf(s[nf][0], s[nf][1]));
            mx1 = fmaxf(mx1, fmaxf(s[nf][2], s[nf][3]));
        }
        mx0 = fmaxf(mx0, __shfl_xor_sync(0xffffffffu, mx0, 1));
        mx0 = fmaxf(mx0, __shfl_xor_sync(0xffffffffu, mx0, 2));
        mx1 = fmaxf(mx1, __shfl_xor_sync(0xffffffffu, mx1, 1));
        mx1 = fmaxf(mx1, __shfl_xor_sync(0xffffffffu, mx1, 2));

        float mn0 = fmaxf(m0r, mx0);
        float mn1 = fmaxf(m1r, mx1);
        float al0 = exp2f(m0r - mn0);
        float al1 = exp2f(m1r - mn1);
        m0r = mn0; m1r = mn1;

        uint32_t pa[4][4];
#pragma unroll
        for (int nf = 0; nf < 8; nf++) {
            __half2 p01 = h2exp2(__floats2half2_rn(s[nf][0] - mn0, s[nf][1] - mn0));
            __half2 p23 = h2exp2(__floats2half2_rn(s[nf][2] - mn1, s[nf][3] - mn1));
            const int ks = nf >> 1;
            const int hi = (nf & 1) * 2;
            pa[ks][hi + 0] = *(const uint32_t*)&p01;
            pa[ks][hi + 1] = *(const uint32_t*)&p23;
        }

#pragma unroll
        for (int nf = 0; nf < 8; nf++) {
            o[nf][0] *= al0; o[nf][1] *= al0;
            o[nf][2] *= al1; o[nf][3] *= al1;
        }
        ol[0] *= al0; ol[1] *= al0; ol[2] *= al1; ol[3] *= al1;

#pragma unroll
        for (int ks = 0; ks < 4; ks++) {
            mma_f16(ol, pa[ks], ones2);
            const uint32_t vrow_h = vbuf_h + (uint32_t)((16 * ks + rb + rr) * 64);
#pragma unroll
            for (int p = 0; p < 4; p++) {
                uint32_t vv[4];
                const uint32_t ch = (uint32_t)(((2 * p + qc) ^ rr) * 8);
                ldmat_x4_t(vv, smb + (vrow_h + ch) * 2);
                mma_f16(o[2 * p + 0], pa[ks], &vv[0]);
                mma_f16(o[2 * p + 1], pa[ks], &vv[2]);
            }
        }
    }

    const int b = bh >> 4;
    const int h = bh & 15;
    const float li0 = 1.0f / ol[0];
    const float li1 = 1.0f / ol[2];
    const int qg0 = qt * 128 + row0;
#pragma unroll
    for (int nf = 0; nf < 8; nf++) {
        int col = h * DKk + nf * 8 + 2 * tig;
        *(__half2*)&out[((size_t)b * TT + qg0) * DM + col] =
            __floats2half2_rn(o[nf][0] * li0, o[nf][1] * li0);
        *(__half2*)&out[((size_t)b * TT + qg0 + 8) * DM + col] =
            __floats2half2_rn(o[nf][2] * li1, o[nf][3] * li1);
    }
}

// ---------------------------------------------------------------------------
extern "C" void kernel_launch(void* const* d_in, const int* in_sizes, int n_in,
                              void* d_out, int out_size)
{
    const float* query = (const float*)d_in[0];
    const float* key   = (const float*)d_in[1];
    const float* value = (const float*)d_in[2];
    // d_in[3] = mask (causal tril, known statically — unused)
    const float* Wq = (const float*)d_in[4];
    const float* bq = (const float*)d_in[5];
    const float* Wk = (const float*)d_in[6];
    const float* bk = (const float*)d_in[7];
    const float* Wv = (const float*)d_in[8];
    const float* bv = (const float*)d_in[9];
    const float* Wo = (const float*)d_in[10];
    const float* bo = (const float*)d_in[11];
    float* out = (float*)d_out;

    __half *q, *k, *v, *ao, *xq, *xk, *xv, *wq, *wk, *wv, *wo;
    cudaGetSymbolAddress((void**)&q,  g_q);
    cudaGetSymbolAddress((void**)&k,  g_k);
    cudaGetSymbolAddress((void**)&v,  g_v);
    cudaGetSymbolAddress((void**)&ao, g_ao);
    cudaGetSymbolAddress((void**)&xq, g_xq);
    cudaGetSymbolAddress((void**)&xk, g_xk);
    cudaGetSymbolAddress((void**)&xv, g_xv);
    cudaGetSymbolAddress((void**)&wq, g_wq);
    cudaGetSymbolAddress((void**)&wk, g_wk);
    cudaGetSymbolAddress((void**)&wv, g_wv);
    cudaGetSymbolAddress((void**)&wo, g_wo);

    cudaFuncSetAttribute(gemm_head_kernel,
                         cudaFuncAttributeMaxDynamicSharedMemorySize, GEMM_SMEM_BYTES);
    cudaFuncSetAttribute(gemm_out_half_kernel,
                         cudaFuncAttributeMaxDynamicSharedMemorySize, GEMM_SMEM_BYTES);
    cudaFuncSetAttribute(flash_f16_kernel,
                         cudaFuncAttributeMaxDynamicSharedMemorySize, FA_SMEM_BYTES);

    static cudaStream_t s1 = nullptr, s2 = nullptr, s3 = nullptr;
    static cudaEvent_t ef = nullptr, ej1 = nullptr, ej2 = nullptr, ej3 = nullptr,
                       eL = nullptr, ej4 = nullptr;
    if (!s1) {
        cudaStreamCreateWithFlags(&s1, cudaStreamNonBlocking);
        cudaStreamCreateWithFlags(&s2, cudaStreamNonBlocking);
        cudaStreamCreateWithFlags(&s3, cudaStreamNonBlocking);
        cudaEventCreateWithFlags(&ef,  cudaEventDisableTiming);
        cudaEventCreateWithFlags(&ej1, cudaEventDisableTiming);
        cudaEventCreateWithFlags(&ej2, cudaEventDisableTiming);
        cudaEventCreateWithFlags(&ej3, cudaEventDisableTiming);
        cudaEventCreateWithFlags(&eL,  cudaEventDisableTiming);
        cudaEventCreateWithFlags(&ej4, cudaEventDisableTiming);
    }

    const int M = BB * TT;               // 8192
    const int NX4 = M * DM / 4;
    const int NW4 = DM * DM / 4;
    dim3 gemm_grid(DM / 128, M / 128);   // (8, 64)
    dim3 rgrid(512, 2);
    const float qscale = 0.125f * 1.4426950408889634f;

    // Fork
    cudaEventRecord(ef, 0);
    cudaStreamWaitEvent(s1, ef, 0);
    cudaStreamWaitEvent(s2, ef, 0);
    cudaStreamWaitEvent(s3, ef, 0);

    // Q chain (stream 0)
    cvt2_kernel<<<rgrid, 256, 0, 0>>>((const float4*)query, (__half2*)xq, NX4,
                                      (const float4*)Wq, (__half2*)wq, NW4);
    gemm_head_kernel<<<gemm_grid, 256, GEMM_SMEM_BYTES, 0>>>(xq, wq, bq, q, qscale);

    // K chain (s1)
    cvt2_kernel<<<rgrid, 256, 0, s1>>>((const float4*)key, (__half2*)xk, NX4,
                                       (const float4*)Wk, (__half2*)wk, NW4);
    gemm_head_kernel<<<gemm_grid, 256, GEMM_SMEM_BYTES, s1>>>(xk, wk, bk, k, 1.0f);
    cudaEventRecord(ej1, s1);

    // V chain (s2)
    cvt2_kernel<<<rgrid, 256, 0, s2>>>((const float4*)value, (__half2*)xv, NX4,
                                       (const float4*)Wv, (__half2*)wv, NW4);
    gemm_head_kernel<<<gemm_grid, 256, GEMM_SMEM_BYTES, s2>>>(xv, wv, bv, v, 1.0f);
    cudaEventRecord(ej2, s2);

    // Wo conversion (s3)
    cvt2_kernel<<<dim3(512, 1), 256, 0, s3>>>((const float4*)Wo, (__half2*)wo, NW4,
                                              (const float4*)Wo, (__half2*)wo, 0);
    cudaEventRecord(ej3, s3);

    // Join K and V before flash
    cudaStreamWaitEvent(0, ej1, 0);
    cudaStreamWaitEvent(0, ej2, 0);

    // Flash split: light half (qt 0..7) first, then heavy half (qt 8..15).
    dim3 fa_grid(8, BB * HH);            // (8, 64)
    flash_f16_kernel<<<fa_grid, 256, FA_SMEM_BYTES, 0>>>(q, k, v, ao, 0);
    cudaEventRecord(eL, 0);
    flash_f16_kernel<<<fa_grid, 256, FA_SMEM_BYTES, 0>>>(q, k, v, ao, 8);

    // Output projection half A (rows t<1024) overlaps the heavy flash half.
    cudaStreamWaitEvent(s1, eL, 0);
    cudaStreamWaitEvent(s1, ej3, 0);
    dim3 out_half_grid(DM / 128, 32);    // (8, 32)
    gemm_out_half_kernel<<<out_half_grid, 256, GEMM_SMEM_BYTES, s1>>>(ao, wo, bo, out, 0);
    cudaEventRecord(ej4, s1);

    // Output projection half B (rows t>=1024) after heavy flash; join s1.
    cudaStreamWaitEvent(0, ej3, 0);
    gemm_out_half_kernel<<<out_half_grid, 256, GEMM_SMEM_BYTES, 0>>>(ao, wo, bo, out, 1);
    cudaStreamWaitEvent(0, ej4, 0);
}

// round 14
// speedup vs baseline: 1.1894x; 1.0986x over previous
#include <cuda_runtime.h>
#include <cuda_fp16.h>
#include <cstdint>

#define BB 4
#define TT 2048
#define HH 16
#define DKk 64
#define DM 1024

// Scratch (static device globals: allocation-free, graph-capture safe)
__device__ __half g_q[BB * HH * TT * DKk];   // [B,H,T,Dk], scaled by 0.125*log2(e)
__device__ __half g_k[BB * HH * TT * DKk];
__device__ __half g_v[BB * HH * TT * DKk];
__device__ __half g_ao[BB * TT * DM];        // [B,T,D]
// fp16 copies of GEMM inputs
__device__ __half g_xq[BB * TT * DM];
__device__ __half g_xk[BB * TT * DM];
__device__ __half g_xv[BB * TT * DM];
__device__ __half g_wq[DM * DM];
__device__ __half g_wk[DM * DM];
__device__ __half g_wv[DM * DM];
__device__ __half g_wo[DM * DM];

// ---------------------------------------------------------------------------
// Baseline-PTX helpers (harness ptxas targets plain sm_103: no tcgen05;
// mma.sync m16n8k16 f16 + cp.async + ldmatrix are fine)
// ---------------------------------------------------------------------------
__device__ __forceinline__ void cp_async16(uint32_t s, const void* g) {
    asm volatile("cp.async.cg.shared.global [%0], [%1], 16;\n" :: "r"(s), "l"(g));
}
__device__ __forceinline__ void cp_commit() {
    asm volatile("cp.async.commit_group;\n" ::: "memory");
}
__device__ __forceinline__ void cp_wait1() {
    asm volatile("cp.async.wait_group 1;\n" ::: "memory");
}

__device__ __forceinline__ void ldmat_x4(uint32_t* r, uint32_t addr) {
    asm volatile("ldmatrix.sync.aligned.m8n8.x4.shared.b16 {%0,%1,%2,%3}, [%4];"
                 : "=r"(r[0]), "=r"(r[1]), "=r"(r[2]), "=r"(r[3]) : "r"(addr));
}
__device__ __forceinline__ void ldmat_x4_t(uint32_t* r, uint32_t addr) {
    asm volatile("ldmatrix.sync.aligned.m8n8.x4.trans.shared.b16 {%0,%1,%2,%3}, [%4];"
                 : "=r"(r[0]), "=r"(r[1]), "=r"(r[2]), "=r"(r[3]) : "r"(addr));
}

// D += A(16x16 f16, row) * B(16x8 f16, col), fp32 accumulate
__device__ __forceinline__ void mma_f16(float* c, const uint32_t* a, const uint32_t* b) {
    asm volatile(
        "mma.sync.aligned.m16n8k16.row.col.f32.f16.f16.f32 "
        "{%0,%1,%2,%3}, {%4,%5,%6,%7}, {%8,%9}, {%0,%1,%2,%3};"
        : "+f"(c[0]), "+f"(c[1]), "+f"(c[2]), "+f"(c[3])
        : "r"(a[0]), "r"(a[1]), "r"(a[2]), "r"(a[3]), "r"(b[0]), "r"(b[1]));
}

// ---------------------------------------------------------------------------
// fp32 -> fp16 conversion pre-pass: two arrays per launch (blockIdx.y selects)
// ---------------------------------------------------------------------------
__global__ __launch_bounds__(256)
void cvt2_kernel(const float4* __restrict__ in0, __half2* __restrict__ out0, int n0,
                 const float4* __restrict__ in1, __half2* __restrict__ out1, int n1)
{
    const float4* in = blockIdx.y ? in1 : in0;
    __half2* out = blockIdx.y ? out1 : out0;
    const int n4 = blockIdx.y ? n1 : n0;
    int i = blockIdx.x * blockDim.x + threadIdx.x;
    const int stride = gridDim.x * blockDim.x;
    for (; i < n4; i += stride) {
        float4 v = in[i];
        out[2 * i + 0] = __floats2half2_rn(v.x, v.y);
        out[2 * i + 1] = __floats2half2_rn(v.z, v.w);
    }
}

// ---------------------------------------------------------------------------
// Tensor-core fp16 GEMM body (round-11 proven config):
// CTA 128x128, BK=64, 3-stage cp.async, 8 warps (2x4), warp tile 64x32,
// XOR-swizzled 64-half rows, 2 CTAs/SM.
// ---------------------------------------------------------------------------
#define STG_HALVES (2 * 128 * 64)
#define GEMM_SMEM_BYTES (3 * STG_HALVES * 2)   // 98304

template <int HEAD_LAYOUT>
__device__ __forceinline__
void gemm_body(const __half* __restrict__ X, const __half* __restrict__ W,
               const float* __restrict__ bias, void* __restrict__ outv,
               int N, int K, float scale, int m0, int n0)
{
    extern __shared__ __half smh[];
    const uint32_t smb = (uint32_t)__cvta_generic_to_shared(smh);
    const int tid = threadIdx.x;
    const int wid = tid >> 5;
    const int lane = tid & 31;
    const int g = lane >> 2;
    const int tig = lane & 3;
    const int q8 = lane >> 3;
    const int rr = lane & 7;
    const int qc = q8 >> 1;
    const int rb = (q8 & 1) * 8;
    const int wm = wid >> 2;
    const int wn = wid & 3;
    const int KT = K >> 6;

    uint32_t arow[4], brow[2];
#pragma unroll
    for (int fm = 0; fm < 4; fm++)
        arow[fm] = (uint32_t)((wm * 64 + fm * 16 + rb + rr) * 64);
#pragma unroll
    for (int p = 0; p < 2; p++)
        brow[p] = (uint32_t)(128 * 64 + (wn * 32 + p * 16 + rb + rr) * 64);

    auto load_tile = [&](int tile) {
        const int k0 = tile << 6;
        const uint32_t base = smb + (uint32_t)(tile % 3) * (STG_HALVES * 2);
#pragma unroll
        for (int i = 0; i < 4; i++) {
            int idx = tid + (i << 8);
            int r = idx >> 3;
            int c = idx & 7;
            uint32_t off = (uint32_t)((r * 64 + ((c ^ (r & 7)) * 8)) * 2);
            cp_async16(base + off, X + (size_t)(m0 + r) * K + k0 + c * 8);
            cp_async16(base + 128 * 64 * 2 + off, W + (size_t)(n0 + r) * K + k0 + c * 8);
        }
    };

    load_tile(0); cp_commit();
    load_tile(1); cp_commit();

    float acc[4][4][4];
#pragma unroll
    for (int fm = 0; fm < 4; fm++)
#pragma unroll
        for (int fn = 0; fn < 4; fn++)
#pragma unroll
            for (int e = 0; e < 4; e++) acc[fm][fn][e] = 0.0f;

    for (int kt = 0; kt < KT; kt++) {
        cp_wait1();
        __syncthreads();
        if (kt + 2 < KT) load_tile(kt + 2);
        cp_commit();

        const uint32_t stage = smb + (uint32_t)(kt % 3) * (STG_HALVES * 2);

#pragma unroll
        for (int ks = 0; ks < 4; ks++) {
            const uint32_t ch = (uint32_t)((((2 * ks + qc) ^ rr) * 8) * 2);
            uint32_t a[4][4], bb[2][4];
#pragma unroll
            for (int fm = 0; fm < 4; fm++) ldmat_x4(a[fm], stage + arow[fm] * 2 + ch);
#pragma unroll
            for (int p = 0; p < 2; p++) ldmat_x4(bb[p], stage + brow[p] * 2 + ch);
#pragma unroll
            for (int fm = 0; fm < 4; fm++)
#pragma unroll
                for (int fn = 0; fn < 4; fn++) {
                    uint32_t b2[2] = {bb[fn >> 1][fn & 1], bb[fn >> 1][2 + (fn & 1)]};
                    mma_f16(acc[fm][fn], a[fm], b2);
                }
        }
    }

#pragma unroll
    for (int fm = 0; fm < 4; fm++) {
#pragma unroll
        for (int fn = 0; fn < 4; fn++) {
            int n = n0 + wn * 32 + fn * 8 + 2 * tig;
            float bx = __ldg(&bias[n]);
            float by = __ldg(&bias[n + 1]);
#pragma unroll
            for (int half = 0; half < 2; half++) {
                int m = m0 + wm * 64 + fm * 16 + g + half * 8;
                float ox = (acc[fm][fn][half * 2 + 0] + bx) * scale;
                float oy = (acc[fm][fn][half * 2 + 1] + by) * scale;
                if (HEAD_LAYOUT) {
                    __half* out = (__half*)outv;
                    int b = m / TT, t = m % TT;
                    int h = n / DKk, dk = n % DKk;
                    *(__half2*)&out[(((size_t)b * HH + h) * TT + t) * DKk + dk] =
                        __floats2half2_rn(ox, oy);
                } else {
                    float* out = (float*)outv;
                    *(float2*)&out[(size_t)m * N + n] = make_float2(ox, oy);
                }
            }
        }
    }
}

// Head-layout projection GEMM over HALF the rows:
// row_half=0 -> t in [0,1024), 1 -> [1024,2048). blockIdx.y in [0,32).
__global__ __launch_bounds__(256, 2)
void gemm_head_half_kernel(const __half* __restrict__ X, const __half* __restrict__ W,
                           const float* __restrict__ bias, __half* __restrict__ out,
                           float scale, int row_half)
{
    const int y = blockIdx.y;
    const int m0 = (y >> 3) * TT + row_half * 1024 + (y & 7) * 128;
    gemm_body<1>(X, W, bias, out, DM, DM, scale, m0, blockIdx.x * 128);
}

// Output GEMM over HALF the rows (fp32 out).
__global__ __launch_bounds__(256, 2)
void gemm_out_half_kernel(const __half* __restrict__ X, const __half* __restrict__ W,
                          const float* __restrict__ bias, float* __restrict__ out,
                          int row_half)
{
    const int y = blockIdx.y;
    const int m0 = (y >> 3) * TT + row_half * 1024 + (y & 7) * 128;
    gemm_body<0>(X, W, bias, out, DM, DM, 1.0f, m0, blockIdx.x * 128);
}

// ---------------------------------------------------------------------------
// Tensor-core fp16 flash attention (round-11 config + qt_base for split
// launches). BQ=128, BK=64, triple-buffered KV, 8 warps, register-resident P,
// l via mma vs ones, heavy q-tiles first within each launch. smem = 65536 B.
// ---------------------------------------------------------------------------
#define Q_OFF 0
#define K_OFF (128 * 64)
#define KVBUF (64 * 64)
#define V_OFF (K_OFF + 3 * KVBUF)
#define FA_HALVES (V_OFF + 3 * KVBUF)
#define FA_SMEM_BYTES (FA_HALVES * 2)          // 65536

__global__ __launch_bounds__(256, 2)
void flash_f16_kernel(const __half* __restrict__ Q, const __half* __restrict__ K,
                      const __half* __restrict__ V, __half* __restrict__ out,
                      int qt_base)
{
    extern __shared__ __half smh[];
    const uint32_t smb = (uint32_t)__cvta_generic_to_shared(smh);
    const int tid = threadIdx.x;
    const int wid = tid >> 5;
    const int lane = tid & 31;
    const int g = lane >> 2;
    const int tig = lane & 3;
    const int q8 = lane >> 3;
    const int rr = lane & 7;
    const int qc = q8 >> 1;
    const int rb = (q8 & 1) * 8;
    const int qt = qt_base + gridDim.x - 1 - blockIdx.x;   // heavy tiles first
    const int bh = blockIdx.y;

    const __half* Qb = Q + ((size_t)bh * TT + qt * 128) * DKk;
    const __half* Kb = K + (size_t)bh * TT * DKk;
    const __half* Vb = V + (size_t)bh * TT * DKk;

#pragma unroll
    for (int i = 0; i < 4; i++) {
        int idx = tid + (i << 8);
        int r = idx >> 3;
        int c = idx & 7;
        uint32_t dst = smb + (uint32_t)((r * 64 + ((c ^ (r & 7)) * 8)) * 2);
        cp_async16(dst, Qb + r * 64 + c * 8);
    }

    auto load_kv = [&](int kt) {
        const int buf = kt % 3;
        const __half* kp = Kb + (size_t)kt * 64 * DKk;
        const __half* vp = Vb + (size_t)kt * 64 * DKk;
#pragma unroll
        for (int i = 0; i < 2; i++) {
            int idx = tid + (i << 8);
            int r = idx >> 3;
            int c = idx & 7;
            uint32_t off = (uint32_t)((r * 64 + ((c ^ (r & 7)) * 8)) * 2);
            uint32_t src_off = (uint32_t)(r * 64 + c * 8);
            cp_async16(smb + (K_OFF + buf * KVBUF) * 2 + off, kp + src_off);
            cp_async16(smb + (V_OFF + buf * KVBUF) * 2 + off, vp + src_off);
        }
    };

    load_kv(0);
    cp_commit();
    load_kv(1);
    cp_commit();

    cp_wait1();
    __syncthreads();
    const uint32_t qrow_h = (uint32_t)((wid * 16 + rb + rr) * 64);
    uint32_t qf[4][4];
#pragma unroll
    for (int ks = 0; ks < 4; ks++) {
        const uint32_t ch = (uint32_t)(((2 * ks + qc) ^ rr) * 8);
        ldmat_x4(qf[ks], smb + (qrow_h + ch) * 2);
    }

    float m0r = -1e30f, m1r = -1e30f;
    float o[8][4], ol[4];
#pragma unroll
    for (int nf = 0; nf < 8; nf++)
#pragma unroll
        for (int e = 0; e < 4; e++) o[nf][e] = 0.0f;
#pragma unroll
    for (int e = 0; e < 4; e++) ol[e] = 0.0f;

    const uint32_t ones2[2] = {0x3C003C00u, 0x3C003C00u};
    const int nkt = 2 * qt + 2;
    const int row0 = wid * 16 + g;

    for (int kt = 0; kt < nkt; kt++) {
        if (kt) { cp_wait1(); __syncthreads(); }
        if (kt + 2 < nkt) load_kv(kt + 2);
        cp_commit();

        const int buf = kt % 3;
        const uint32_t kbuf_h = (uint32_t)(K_OFF + buf * KVBUF);
        const uint32_t vbuf_h = (uint32_t)(V_OFF + buf * KVBUF);

        float s[8][4];
#pragma unroll
        for (int nf = 0; nf < 8; nf++)
#pragma unroll
            for (int e = 0; e < 4; e++) s[nf][e] = 0.0f;

#pragma unroll
        for (int ks = 0; ks < 4; ks++) {
            uint32_t bb[4][4];
            const uint32_t ch = (uint32_t)(((2 * ks + qc) ^ rr) * 8);
#pragma unroll
            for (int p = 0; p < 4; p++) {
                uint32_t krow_h = kbuf_h + (uint32_t)((p * 16 + rb + rr) * 64);
                ldmat_x4(bb[p], smb + (krow_h + ch) * 2);
            }
#pragma unroll
            for (int nf = 0; nf < 8; nf++) {
                uint32_t b2[2] = {bb[nf >> 1][nf & 1], bb[nf >> 1][2 + (nf & 1)]};
                mma_f16(s[nf], qf[ks], b2);
            }
        }

        if (kt >= 2 * qt) {
            const int qg0 = qt * 128 + row0;
            const int qg1 = qg0 + 8;
#pragma unroll
            for (int nf = 0; nf < 8; nf++) {
                int kg = kt * 64 + nf * 8 + 2 * tig;
                if (kg > qg0) s[nf][0] = -1e30f;
                if (kg + 1 > qg0) s[nf][1] = -1e30f;
                if (kg > qg1) s[nf][2] = -1e30f;
                if (kg + 1 > qg1) s[nf][3] = -1e30f;
            }
        }

        float mx0 = -1e30f, mx1 = -1e30f;
#pragma unroll
        for (int nf = 0; nf < 8; nf++) {
            mx0 = fmaxf(mx0, fmaxf(s[nf][0], s[nf][1]));
            mx1 = fmaxf(mx1, fmaxf(s[nf][2], s[nf][3]));
        }
        mx0 = fmaxf(mx0, __shfl_xor_sync(0xffffffffu, mx0, 1));
        mx0 = fmaxf(mx0, __shfl_xor_sync(0xffffffffu, mx0, 2));
        mx1 = fmaxf(mx1, __shfl_xor_sync(0xffffffffu, mx1, 1));
        mx1 = fmaxf(mx1, __shfl_xor_sync(0xffffffffu, mx1, 2));

        float mn0 = fmaxf(m0r, mx0);
        float mn1 = fmaxf(m1r, mx1);
        float al0 = exp2f(m0r - mn0);
        float al1 = exp2f(m1r - mn1);
        m0r = mn0; m1r = mn1;

        uint32_t pa[4][4];
#pragma unroll
        for (int nf = 0; nf < 8; nf++) {
            __half2 p01 = h2exp2(__floats2half2_rn(s[nf][0] - mn0, s[nf][1] - mn0));
            __half2 p23 = h2exp2(__floats2half2_rn(s[nf][2] - mn1, s[nf][3] - mn1));
            const int ks = nf >> 1;
            const int hi = (nf & 1) * 2;
            pa[ks][hi + 0] = *(const uint32_t*)&p01;
            pa[ks][hi + 1] = *(const uint32_t*)&p23;
        }

#pragma unroll
        for (int nf = 0; nf < 8; nf++) {
            o[nf][0] *= al0; o[nf][1] *= al0;
            o[nf][2] *= al1; o[nf][3] *= al1;
        }
        ol[0] *= al0; ol[1] *= al0; ol[2] *= al1; ol[3] *= al1;

#pragma unroll
        for (int ks = 0; ks < 4; ks++) {
            mma_f16(ol, pa[ks], ones2);
            const uint32_t vrow_h = vbuf_h + (uint32_t)((16 * ks + rb + rr) * 64);
#pragma unroll
            for (int p = 0; p < 4; p++) {
                uint32_t vv[4];
                const uint32_t ch = (uint32_t)(((2 * p + qc) ^ rr) * 8);
                ldmat_x4_t(vv, smb + (vrow_h + ch) * 2);
                mma_f16(o[2 * p + 0], pa[ks], &vv[0]);
                mma_f16(o[2 * p + 1], pa[ks], &vv[2]);
            }
        }
    }

    const int b = bh >> 4;
    const int h = bh & 15;
    const float li0 = 1.0f / ol[0];
    const float li1 = 1.0f / ol[2];
    const int qg0 = qt * 128 + row0;
#pragma unroll
    for (int nf = 0; nf < 8; nf++) {
        int col = h * DKk + nf * 8 + 2 * tig;
        *(__half2*)&out[((size_t)b * TT + qg0) * DM + col] =
            __floats2half2_rn(o[nf][0] * li0, o[nf][1] * li0);
        *(__half2*)&out[((size_t)b * TT + qg0 + 8) * DM + col] =
            __floats2half2_rn(o[nf][2] * li1, o[nf][3] * li1);
    }
}

// ---------------------------------------------------------------------------
extern "C" void kernel_launch(void* const* d_in, const int* in_sizes, int n_in,
                              void* d_out, int out_size)
{
    const float* query = (const float*)d_in[0];
    const float* key   = (const float*)d_in[1];
    const float* value = (const float*)d_in[2];
    // d_in[3] = mask (causal tril, known statically — unused)
    const float* Wq = (const float*)d_in[4];
    const float* bq = (const float*)d_in[5];
    const float* Wk = (const float*)d_in[6];
    const float* bk = (const float*)d_in[7];
    const float* Wv = (const float*)d_in[8];
    const float* bv = (const float*)d_in[9];
    const float* Wo = (const float*)d_in[10];
    const float* bo = (const float*)d_in[11];
    float* out = (float*)d_out;

    __half *q, *k, *v, *ao, *xq, *xk, *xv, *wq, *wk, *wv, *wo;
    cudaGetSymbolAddress((void**)&q,  g_q);
    cudaGetSymbolAddress((void**)&k,  g_k);
    cudaGetSymbolAddress((void**)&v,  g_v);
    cudaGetSymbolAddress((void**)&ao, g_ao);
    cudaGetSymbolAddress((void**)&xq, g_xq);
    cudaGetSymbolAddress((void**)&xk, g_xk);
    cudaGetSymbolAddress((void**)&xv, g_xv);
    cudaGetSymbolAddress((void**)&wq, g_wq);
    cudaGetSymbolAddress((void**)&wk, g_wk);
    cudaGetSymbolAddress((void**)&wv, g_wv);
    cudaGetSymbolAddress((void**)&wo, g_wo);

    cudaFuncSetAttribute(gemm_head_half_kernel,
                         cudaFuncAttributeMaxDynamicSharedMemorySize, GEMM_SMEM_BYTES);
    cudaFuncSetAttribute(gemm_out_half_kernel,
                         cudaFuncAttributeMaxDynamicSharedMemorySize, GEMM_SMEM_BYTES);
    cudaFuncSetAttribute(flash_f16_kernel,
                         cudaFuncAttributeMaxDynamicSharedMemorySize, FA_SMEM_BYTES);

    static cudaStream_t s1 = nullptr, s2 = nullptr, s3 = nullptr;
    static cudaEvent_t ef = nullptr, eQA = nullptr, eKA = nullptr, eVA = nullptr,
                       ej1 = nullptr, ej2 = nullptr, ej3 = nullptr,
                       eLF = nullptr, ej4 = nullptr;
    if (!s1) {
        cudaStreamCreateWithFlags(&s1, cudaStreamNonBlocking);
        cudaStreamCreateWithFlags(&s2, cudaStreamNonBlocking);
        cudaStreamCreateWithFlags(&s3, cudaStreamNonBlocking);
        cudaEventCreateWithFlags(&ef,  cudaEventDisableTiming);
        cudaEventCreateWithFlags(&eQA, cudaEventDisableTiming);
        cudaEventCreateWithFlags(&eKA, cudaEventDisableTiming);
        cudaEventCreateWithFlags(&eVA, cudaEventDisableTiming);
        cudaEventCreateWithFlags(&ej1, cudaEventDisableTiming);
        cudaEventCreateWithFlags(&ej2, cudaEventDisableTiming);
        cudaEventCreateWithFlags(&ej3, cudaEventDisableTiming);
        cudaEventCreateWithFlags(&eLF, cudaEventDisableTiming);
        cudaEventCreateWithFlags(&ej4, cudaEventDisableTiming);
    }

    const int M = BB * TT;               // 8192
    const int NX4 = M * DM / 4;
    const int NW4 = DM * DM / 4;
    dim3 half_grid(DM / 128, 32);        // (8, 32) = 256 CTAs per half
    dim3 rgrid(512, 2);
    const float qscale = 0.125f * 1.4426950408889634f;

    // Fork
    cudaEventRecord(ef, 0);
    cudaStreamWaitEvent(s1, ef, 0);
    cudaStreamWaitEvent(s2, ef, 0);
    cudaStreamWaitEvent(s3, ef, 0);

    // Q chain (stream 0): cvt -> halfA (event) -> halfB
    cvt2_kernel<<<rgrid, 256, 0, 0>>>((const float4*)query, (__half2*)xq, NX4,
                                      (const float4*)Wq, (__half2*)wq, NW4);
    gemm_head_half_kernel<<<half_grid, 256, GEMM_SMEM_BYTES, 0>>>(xq, wq, bq, q, qscale, 0);
    cudaEventRecord(eQA, 0);
    gemm_head_half_kernel<<<half_grid, 256, GEMM_SMEM_BYTES, 0>>>(xq, wq, bq, q, qscale, 1);

    // K chain (s1)
    cvt2_kernel<<<rgrid, 256, 0, s1>>>((const float4*)key, (__half2*)xk, NX4,
                                       (const float4*)Wk, (__half2*)wk, NW4);
    gemm_head_half_kernel<<<half_grid, 256, GEMM_SMEM_BYTES, s1>>>(xk, wk, bk, k, 1.0f, 0);
    cudaEventRecord(eKA, s1);
    gemm_head_half_kernel<<<half_grid, 256, GEMM_SMEM_BYTES, s1>>>(xk, wk, bk, k, 1.0f, 1);
    cudaEventRecord(ej1, s1);

    // V chain (s2)
    cvt2_kernel<<<rgrid, 256, 0, s2>>>((const float4*)value, (__half2*)xv, NX4,
                                       (const float4*)Wv, (__half2*)wv, NW4);
    gemm_head_half_kernel<<<half_grid, 256, GEMM_SMEM_BYTES, s2>>>(xv, wv, bv, v, 1.0f, 0);
    cudaEventRecord(eVA, s2);
    gemm_head_half_kernel<<<half_grid, 256, GEMM_SMEM_BYTES, s2>>>(xv, wv, bv, v, 1.0f, 1);
    cudaEventRecord(ej2, s2);

    // Wo conversion (s3), then LIGHT flash (qt 0..7: needs only t<1024 of q/k/v)
    cvt2_kernel<<<dim3(512, 1), 256, 0, s3>>>((const float4*)Wo, (__half2*)wo, NW4,
                                              (const float4*)Wo, (__half2*)wo, 0);
    cudaEventRecord(ej3, s3);
    cudaStreamWaitEvent(s3, eQA, 0);
    cudaStreamWaitEvent(s3, eKA, 0);
    cudaStreamWaitEvent(s3, eVA, 0);
    dim3 fa_grid(8, BB * HH);            // (8, 64)
    flash_f16_kernel<<<fa_grid, 256, FA_SMEM_BYTES, s3>>>(q, k, v, ao, 0);
    cudaEventRecord(eLF, s3);

    // HEAVY flash (qt 8..15) on stream 0: Q halfB in-order; wait full K,V.
    cudaStreamWaitEvent(0, ej1, 0);
    cudaStreamWaitEvent(0, ej2, 0);
    flash_f16_kernel<<<fa_grid, 256, FA_SMEM_BYTES, 0>>>(q, k, v, ao, 8);

    // Output projection half A (rows t<1024) overlaps heavy flash (s1).
    cudaStreamWaitEvent(s1, eLF, 0);
    cudaStreamWaitEvent(s1, ej3, 0);
    gemm_out_half_kernel<<<half_grid, 256, GEMM_SMEM_BYTES, s1>>>(ao, wo, bo, out, 0);
    cudaEventRecord(ej4, s1);

    // Output projection half B (rows t>=1024) after heavy flash; join s1.
    cudaStreamWaitEvent(0, ej3, 0);
    gemm_out_half_kernel<<<half_grid, 256, GEMM_SMEM_BYTES, 0>>>(ao, wo, bo, out, 1);
    cudaStreamWaitEvent(0, ej4, 0);
}